// round 10
// baseline (speedup 1.0000x reference)
#include <cuda_runtime.h>
#include <cuda_fp16.h>
#include <math.h>
#include <stdint.h>

#define BATCH 64
#define S 512
#define D 768
#define W 256
#define KX 1536     // 2*D router input
#define H 256       // router hidden (= GEMM N)
#define L 7
#define ROWS (BATCH * W)   // 16384
#define CTA_M 64
#define KT2 64             // K-tile (fp16 elems) = 128 bytes = one SW128 row
#define NITER (KX / KT2)   // 24
#define NSTAGE 4

// stage layout (bytes): A 8K | B 32K
#define OFF_A 0u
#define OFF_B 8192u
#define STAGE_BYTES 40960u
#define OFF_TILES 4096u
#define SMEM_TOTAL (OFF_TILES + NSTAGE * STAGE_BYTES)   // 167936

// fp16 operands (single rounding)
__device__ __align__(16) __half g_xh[(size_t)ROWS * KX];
__device__ __align__(16) __half g_w1[(size_t)H * KX];   // [n][k]

__device__ __forceinline__ uint32_t smem_u32(const void* p) {
    uint32_t a;
    asm("{ .reg .u64 t; cvta.to.shared.u64 t, %1; cvt.u32.u64 %0, t; }"
        : "=r"(a) : "l"(p));
    return a;
}
#define SWZ(x) ((x) ^ (((x) >> 3) & 0x70))
__device__ __forceinline__ void cp16(uint32_t dst, const void* src) {
    asm volatile("cp.async.cg.shared.global [%0], [%1], 16;" :: "r"(dst), "l"(src));
}
#define CP_COMMIT() asm volatile("cp.async.commit_group;" ::: "memory")

#define LDSM_X4(R, A)                                                        \
    asm volatile("ldmatrix.sync.aligned.m8n8.x4.shared.b16 {%0,%1,%2,%3}, [%4];" \
        : "=r"((R)[0]), "=r"((R)[1]), "=r"((R)[2]), "=r"((R)[3]) : "r"(A))

#define MMA_F16(Dd, Aa, Bb)                                                  \
    asm volatile("mma.sync.aligned.m16n8k16.row.col.f32.f16.f16.f32 "        \
        "{%0,%1,%2,%3}, {%4,%5,%6,%7}, {%8,%9}, {%0,%1,%2,%3};"              \
        : "+f"((Dd)[0]), "+f"((Dd)[1]), "+f"((Dd)[2]), "+f"((Dd)[3])         \
        : "r"((Aa)[0]), "r"((Aa)[1]), "r"((Aa)[2]), "r"((Aa)[3]),            \
          "r"((Bb)[0]), "r"((Bb)[1]))

// ---------------------------------------------------------------------------
// Align + prep in ONE grid: blocks [0,4096) do align (one warp per
// (row,source) unit, R6 structure); blocks [4096, 4096+1536) transpose/round
// W1. Concurrent, no serialized launch, no per-block imbalance.
// Search: lo/hi interleaved lower_bounds, 10 halving steps (512 -> 0).
// ---------------------------------------------------------------------------
__global__ __launch_bounds__(256) void align_kernel(
    const float* __restrict__ hing, const float* __restrict__ rob,
    const int* __restrict__ hids, const int* __restrict__ rids,
    const float* __restrict__ w1)
{
    int tid = threadIdx.x;
    int bid = blockIdx.x;

    if (bid >= (ROWS * 2) / 8) {                    // prep_w1 blocks
        int idx = (bid - (ROWS * 2) / 8) * 256 + tid;   // n*KX + k
        int n = idx / KX;
        int k = idx - n * KX;
        g_w1[idx] = __float2half_rn(w1[(size_t)k * H + n]);
        return;
    }

    int unit = bid * 8 + (tid >> 5);   // 0 .. ROWS*2-1
    int lane = tid & 31;
    int srci = unit & 1;
    int row  = unit >> 1;
    int b = row >> 8;
    int w = row & (W - 1);

    const int* ids = (srci ? rids : hids) + b * S;
    const float* src = srci ? rob : hing;

    // interleaved lower_bound(w) / lower_bound(w+1), 10 steps
    int lo = 0, h = S, hi = 0, g = S;
    #pragma unroll 1
    for (int i = 0; i < 10; i++) {
        int m = (lo + h) >> 1;
        int n = (hi + g) >> 1;
        int a = ids[m < S ? m : S - 1];
        int c = ids[n < S ? n : S - 1];
        if (lo < h) { if (a < w)  lo = m + 1; else h = m; }
        if (hi < g) { if (c <= w) hi = n + 1; else g = n; }
    }

    float inv = (hi > lo) ? 1.0f / (float)(hi - lo) : 0.0f;
    const float4* base = (const float4*)(src + (size_t)b * S * D);
    __half2* dh = (__half2*)(g_xh + (size_t)row * KX + srci * D);

    float4 acc[6];
    #pragma unroll
    for (int t = 0; t < 6; t++) acc[t] = make_float4(0.f, 0.f, 0.f, 0.f);
    #pragma unroll 1
    for (int s = lo; s < hi; s++) {
        const float4* rowp = base + (size_t)s * (D / 4) + lane;
        #pragma unroll
        for (int t = 0; t < 6; t++) {
            float4 v = rowp[32 * t];
            acc[t].x += v.x; acc[t].y += v.y; acc[t].z += v.z; acc[t].w += v.w;
        }
    }
    #pragma unroll
    for (int t = 0; t < 6; t++) {
        int c4 = (lane + 32 * t) * 2;   // half2 index within D
        __half2 p0, p1;
        p0.x = __float2half_rn(acc[t].x * inv);
        p0.y = __float2half_rn(acc[t].y * inv);
        p1.x = __float2half_rn(acc[t].z * inv);
        p1.y = __float2half_rn(acc[t].w * inv);
        dh[c4]     = p0;
        dh[c4 + 1] = p1;
    }
}

// ---------------------------------------------------------------------------
// Router: mma.sync fp16 GEMM (CTA: M=64, N=256, K=1536), 4-stage cp.async
// pipeline, ONE __syncthreads per iteration, 1 CTA/SM.
// + fused alpha / blend / head / l2 epilogue.
// ---------------------------------------------------------------------------
__device__ __forceinline__ void load_tiles(uint32_t st, int kk, int r0, int tid)
{
    const __half* ax = g_xh + (size_t)r0 * KX + kk;
    #pragma unroll
    for (int t = 0; t < 2; t++) {
        int idx = t * 256 + tid;           // 512 chunks: 64 rows x 8
        int r = idx >> 3, c = idx & 7;
        uint32_t sw = SWZ((uint32_t)(r * 128 + c * 16));
        cp16(st + OFF_A + sw, ax + (size_t)r * KX + c * 8);
    }
    const __half* bw = g_w1 + kk;
    #pragma unroll
    for (int t = 0; t < 8; t++) {
        int idx = t * 256 + tid;           // 2048 chunks: 256 rows x 8
        int n = idx >> 3, c = idx & 7;
        uint32_t sw = SWZ((uint32_t)(n * 128 + c * 16));
        cp16(st + OFF_B + sw, bw + (size_t)n * KX + c * 8);
    }
}

__global__ __launch_bounds__(256, 1) void router_kernel(
    const float* __restrict__ b1, const float* __restrict__ w2,
    const float* __restrict__ b2p,
    const float* __restrict__ headw, const float* __restrict__ headb,
    float* __restrict__ out)
{
    extern __shared__ char smem[];
    uint32_t sb = smem_u32(smem);
    int tid = threadIdx.x;
    int wid = tid >> 5, lane = tid & 31;
    int warp_m = wid >> 2;        // 0..1  (rows warp_m*32 .. +32)
    int warp_n = wid & 3;         // 0..3  (cols warp_n*64 .. +64)
    int r0 = blockIdx.x * CTA_M;

    float* s_b1    = (float*)(smem);
    float* s_w2    = (float*)(smem + 1024);
    float* s_part  = (float*)(smem + 2048);   // 64 floats
    float* s_alpha = (float*)(smem + 2304);   // 64 floats

    s_b1[tid] = b1[tid];
    s_w2[tid] = w2[tid];
    if (tid < CTA_M) s_part[tid] = 0.0f;
    float b2 = *b2p;

    // prologue: 3 stages in flight
    #pragma unroll
    for (int p = 0; p < 3; p++) {
        load_tiles(sb + OFF_TILES + (uint32_t)p * STAGE_BYTES, p * KT2, r0, tid);
        CP_COMMIT();
    }

    float acc[2][8][4];
    #pragma unroll
    for (int mi = 0; mi < 2; mi++)
        #pragma unroll
        for (int ni = 0; ni < 8; ni++)
            #pragma unroll
            for (int j = 0; j < 4; j++) acc[mi][ni][j] = 0.0f;

    // per-thread ldmatrix addressing (within tile, pre-swizzle parts)
    int arow  = warp_m * 32 + (lane & 15);
    uint32_t acol = ((uint32_t)(lane >> 4)) * 16;
    int nrow  = warp_n * 64 + (((lane >> 4) & 1) << 3) + (lane & 7);
    uint32_t bcol = (((uint32_t)(lane >> 3)) & 1) << 4;

    for (int it = 0; it < NITER; it++) {
        // stage-it group is complete once at most min(2, NITER-1-it) newer
        // groups remain pending
        if (it < NITER - 2)
            asm volatile("cp.async.wait_group 2;" ::: "memory");
        else if (it == NITER - 2)
            asm volatile("cp.async.wait_group 1;" ::: "memory");
        else
            asm volatile("cp.async.wait_group 0;" ::: "memory");
        __syncthreads();   // single barrier per iteration

        // refill the stage freed at it-1 with data for it+3
        if (it + 3 < NITER) {
            load_tiles(sb + OFF_TILES + (uint32_t)((it + 3) & 3) * STAGE_BYTES,
                       (it + 3) * KT2, r0, tid);
            CP_COMMIT();
        }

        uint32_t st = sb + OFF_TILES + (uint32_t)(it & 3) * STAGE_BYTES;

        #pragma unroll
        for (int ks = 0; ks < 4; ks++) {
            uint32_t kb = (uint32_t)ks * 32;
            uint32_t aa[2][4];
            #pragma unroll
            for (int mi = 0; mi < 2; mi++) {
                uint32_t off = SWZ((uint32_t)((arow + mi * 16) * 128) + acol + kb);
                LDSM_X4(aa[mi], st + OFF_A + off);
            }
            uint32_t bb[8][2];
            #pragma unroll
            for (int g = 0; g < 4; g++) {
                uint32_t off = SWZ((uint32_t)((nrow + g * 16) * 128) + bcol + kb);
                uint32_t rb[4];
                LDSM_X4(rb, st + OFF_B + off);
                bb[2 * g][0] = rb[0]; bb[2 * g][1] = rb[1];
                bb[2 * g + 1][0] = rb[2]; bb[2 * g + 1][1] = rb[3];
            }
            #pragma unroll
            for (int mi = 0; mi < 2; mi++)
                #pragma unroll
                for (int ni = 0; ni < 8; ni++)
                    MMA_F16(acc[mi][ni], aa[mi], bb[ni]);
        }
    }

    // alpha partials: relu(hdn + b1) . w2 over this warp's 64 columns
    #pragma unroll
    for (int mi = 0; mi < 2; mi++) {
        #pragma unroll
        for (int rh = 0; rh < 2; rh++) {
            float part = 0.0f;
            #pragma unroll
            for (int ni = 0; ni < 8; ni++) {
                int col0 = warp_n * 64 + ni * 8 + 2 * (lane & 3);
                float h0 = acc[mi][ni][rh * 2 + 0] + s_b1[col0];
                float h1 = acc[mi][ni][rh * 2 + 1] + s_b1[col0 + 1];
                h0 = h0 > 0.f ? h0 : 0.f;
                h1 = h1 > 0.f ? h1 : 0.f;
                part = fmaf(h0, s_w2[col0], part);
                part = fmaf(h1, s_w2[col0 + 1], part);
            }
            part += __shfl_xor_sync(0xffffffffu, part, 1);
            part += __shfl_xor_sync(0xffffffffu, part, 2);
            if ((lane & 3) == 0)
                atomicAdd(&s_part[warp_m * 32 + mi * 16 + rh * 8 + (lane >> 2)], part);
        }
    }
    __syncthreads();
    if (tid < CTA_M) {
        float z = s_part[tid] + b2;
        s_alpha[tid] = 1.0f / (1.0f + expf(-z));
    }
    __syncthreads();

    // blend/head/l2 epilogue: 8 warps x 8 words
    float* out_logits = out;
    float* out_alpha  = out + (size_t)ROWS * L;
    float* out_l2     = out_alpha + ROWS;

    #pragma unroll 1
    for (int wi = 0; wi < 8; wi++) {
        int li = wid * 8 + wi;
        size_t row = (size_t)(r0 + li);
        float al = s_alpha[li];
        float oma = 1.0f - al;
        const __half2* xh2 = (const __half2*)(g_xh + row * KX);

        float lg[L];
        #pragma unroll
        for (int l = 0; l < L; l++) lg[l] = 0.0f;
        float l2 = 0.0f;

        #pragma unroll 1
        for (int d2 = lane; d2 < D / 2; d2 += 32) {
            __half2 hh2 = xh2[d2];
            __half2 rr2 = xh2[D / 2 + d2];
            float hh[2], hr[2];
            hh[0] = __half2float(hh2.x); hh[1] = __half2float(hh2.y);
            hr[0] = __half2float(rr2.x); hr[1] = __half2float(rr2.y);
            #pragma unroll
            for (int u = 0; u < 2; u++) {
                int d = d2 * 2 + u;
                float bl = al * hh[u] + oma * hr[u];
                float df = hh[u] - hr[u];
                l2 = fmaf(df, df, l2);
                #pragma unroll
                for (int l = 0; l < L; l++)
                    lg[l] = fmaf(bl, headw[(size_t)d * L + l], lg[l]);
            }
        }
        #pragma unroll
        for (int o = 16; o > 0; o >>= 1) {
            #pragma unroll
            for (int l = 0; l < L; l++)
                lg[l] += __shfl_xor_sync(0xffffffffu, lg[l], o);
            l2 += __shfl_xor_sync(0xffffffffu, l2, o);
        }
        if (lane == 0) {
            #pragma unroll
            for (int l = 0; l < L; l++)
                out_logits[row * L + l] = lg[l] + headb[l];
            out_alpha[row] = al;
            out_l2[row] = sqrtf(l2);
        }
    }
}

extern "C" void kernel_launch(void* const* d_in, const int* in_sizes, int n_in,
                              void* d_out, int out_size)
{
    const float* hing = (const float*)d_in[0];
    const float* rob  = (const float*)d_in[1];
    const int*   hids = (const int*)d_in[2];
    const int*   rids = (const int*)d_in[3];
    // d_in[4] = num_words (unused by the reference outputs)
    const float* w1 = (const float*)d_in[5];
    const float* b1 = (const float*)d_in[6];
    const float* w2 = (const float*)d_in[7];
    const float* b2 = (const float*)d_in[8];
    const float* hw = (const float*)d_in[9];
    const float* hb = (const float*)d_in[10];
    float* out = (float*)d_out;

    cudaFuncSetAttribute(router_kernel,
                         cudaFuncAttributeMaxDynamicSharedMemorySize, SMEM_TOTAL);

    align_kernel<<<(ROWS * 2) / 8 + (KX * H) / 256, 256>>>(hing, rob, hids, rids, w1);
    router_kernel<<<ROWS / CTA_M, 256, SMEM_TOTAL>>>(b1, w2, b2, hw, hb, out);
}

// round 11
// speedup vs baseline: 1.1172x; 1.1172x over previous
#include <cuda_runtime.h>
#include <cuda_fp16.h>
#include <math.h>
#include <stdint.h>

#define BATCH 64
#define S 512
#define D 768
#define W 256
#define KX 1536     // 2*D router input
#define H 256       // router hidden (= GEMM N)
#define L 7
#define ROWS (BATCH * W)   // 16384
#define CTA_M 64
#define KT2 64             // K-tile (fp16 elems) = 128 bytes = one SW128 row
#define NITER (KX / KT2)   // 24

// stage layout (bytes): A 8K | B 32K
#define OFF_A 0u
#define OFF_B 8192u
#define STAGE_BYTES 40960u
#define OFF_TILES 4096u
#define SMEM_TOTAL (OFF_TILES + 2 * STAGE_BYTES)   // 86016 -> 2 CTAs/SM

// fp16 operands (single rounding)
__device__ __align__(16) __half g_xh[(size_t)ROWS * KX];
__device__ __align__(16) __half g_w1[(size_t)H * KX];   // [n][k]

__device__ __forceinline__ uint32_t smem_u32(const void* p) {
    uint32_t a;
    asm("{ .reg .u64 t; cvta.to.shared.u64 t, %1; cvt.u32.u64 %0, t; }"
        : "=r"(a) : "l"(p));
    return a;
}
#define SWZ(x) ((x) ^ (((x) >> 3) & 0x70))
__device__ __forceinline__ void cp16(uint32_t dst, const void* src) {
    asm volatile("cp.async.cg.shared.global [%0], [%1], 16;" :: "r"(dst), "l"(src));
}
#define CP_COMMIT() asm volatile("cp.async.commit_group;" ::: "memory")

#define LDSM_X4(R, A)                                                        \
    asm volatile("ldmatrix.sync.aligned.m8n8.x4.shared.b16 {%0,%1,%2,%3}, [%4];" \
        : "=r"((R)[0]), "=r"((R)[1]), "=r"((R)[2]), "=r"((R)[3]) : "r"(A))

#define MMA_F16(Dd, Aa, Bb)                                                  \
    asm volatile("mma.sync.aligned.m16n8k16.row.col.f32.f16.f16.f32 "        \
        "{%0,%1,%2,%3}, {%4,%5,%6,%7}, {%8,%9}, {%0,%1,%2,%3};"              \
        : "+f"((Dd)[0]), "+f"((Dd)[1]), "+f"((Dd)[2]), "+f"((Dd)[3])         \
        : "r"((Aa)[0]), "r"((Aa)[1]), "r"((Aa)[2]), "r"((Aa)[3]),            \
          "r"((Bb)[0]), "r"((Bb)[1]))

// ---------------------------------------------------------------------------
// Align + prep in ONE grid (R10, measured ~54us): blocks [0,4096) do align
// (one warp per (row,source) unit); blocks [4096, 4096+1536) transpose/round
// W1. Interleaved lo/hi lower_bounds, 10 halving steps.
// ---------------------------------------------------------------------------
__global__ __launch_bounds__(256) void align_kernel(
    const float* __restrict__ hing, const float* __restrict__ rob,
    const int* __restrict__ hids, const int* __restrict__ rids,
    const float* __restrict__ w1)
{
    int tid = threadIdx.x;
    int bid = blockIdx.x;

    if (bid >= (ROWS * 2) / 8) {                    // prep_w1 blocks
        int idx = (bid - (ROWS * 2) / 8) * 256 + tid;   // n*KX + k
        int n = idx / KX;
        int k = idx - n * KX;
        g_w1[idx] = __float2half_rn(w1[(size_t)k * H + n]);
        return;
    }

    int unit = bid * 8 + (tid >> 5);   // 0 .. ROWS*2-1
    int lane = tid & 31;
    int srci = unit & 1;
    int row  = unit >> 1;
    int b = row >> 8;
    int w = row & (W - 1);

    const int* ids = (srci ? rids : hids) + b * S;
    const float* src = srci ? rob : hing;

    // interleaved lower_bound(w) / lower_bound(w+1), 10 steps
    int lo = 0, h = S, hi = 0, g = S;
    #pragma unroll 1
    for (int i = 0; i < 10; i++) {
        int m = (lo + h) >> 1;
        int n = (hi + g) >> 1;
        int a = ids[m < S ? m : S - 1];
        int c = ids[n < S ? n : S - 1];
        if (lo < h) { if (a < w)  lo = m + 1; else h = m; }
        if (hi < g) { if (c <= w) hi = n + 1; else g = n; }
    }

    float inv = (hi > lo) ? 1.0f / (float)(hi - lo) : 0.0f;
    const float4* base = (const float4*)(src + (size_t)b * S * D);
    __half2* dh = (__half2*)(g_xh + (size_t)row * KX + srci * D);

    float4 acc[6];
    #pragma unroll
    for (int t = 0; t < 6; t++) acc[t] = make_float4(0.f, 0.f, 0.f, 0.f);
    #pragma unroll 1
    for (int s = lo; s < hi; s++) {
        const float4* rowp = base + (size_t)s * (D / 4) + lane;
        #pragma unroll
        for (int t = 0; t < 6; t++) {
            float4 v = rowp[32 * t];
            acc[t].x += v.x; acc[t].y += v.y; acc[t].z += v.z; acc[t].w += v.w;
        }
    }
    #pragma unroll
    for (int t = 0; t < 6; t++) {
        int c4 = (lane + 32 * t) * 2;   // half2 index within D
        __half2 p0, p1;
        p0.x = __float2half_rn(acc[t].x * inv);
        p0.y = __float2half_rn(acc[t].y * inv);
        p1.x = __float2half_rn(acc[t].z * inv);
        p1.y = __float2half_rn(acc[t].w * inv);
        dh[c4]     = p0;
        dh[c4 + 1] = p1;
    }
}

// ---------------------------------------------------------------------------
// Router (R9/R6, measured 87.7us): mma.sync fp16 GEMM, CTA M=64 N=256 K=1536,
// double-buffered cp.async, 2 CTAs/SM + fused alpha/blend/head/l2 epilogue.
// ---------------------------------------------------------------------------
__device__ __forceinline__ void load_tiles(uint32_t st, int kk, int r0, int tid)
{
    const __half* ax = g_xh + (size_t)r0 * KX + kk;
    #pragma unroll
    for (int t = 0; t < 2; t++) {
        int idx = t * 256 + tid;           // 512 chunks: 64 rows x 8
        int r = idx >> 3, c = idx & 7;
        uint32_t sw = SWZ((uint32_t)(r * 128 + c * 16));
        cp16(st + OFF_A + sw, ax + (size_t)r * KX + c * 8);
    }
    const __half* bw = g_w1 + kk;
    #pragma unroll
    for (int t = 0; t < 8; t++) {
        int idx = t * 256 + tid;           // 2048 chunks: 256 rows x 8
        int n = idx >> 3, c = idx & 7;
        uint32_t sw = SWZ((uint32_t)(n * 128 + c * 16));
        cp16(st + OFF_B + sw, bw + (size_t)n * KX + c * 8);
    }
}

__global__ __launch_bounds__(256, 2) void router_kernel(
    const float* __restrict__ b1, const float* __restrict__ w2,
    const float* __restrict__ b2p,
    const float* __restrict__ headw, const float* __restrict__ headb,
    float* __restrict__ out)
{
    extern __shared__ char smem[];
    uint32_t sb = smem_u32(smem);
    int tid = threadIdx.x;
    int wid = tid >> 5, lane = tid & 31;
    int warp_m = wid >> 2;        // 0..1  (rows warp_m*32 .. +32)
    int warp_n = wid & 3;         // 0..3  (cols warp_n*64 .. +64)
    int r0 = blockIdx.x * CTA_M;

    float* s_b1    = (float*)(smem);
    float* s_w2    = (float*)(smem + 1024);
    float* s_part  = (float*)(smem + 2048);   // 64 floats
    float* s_alpha = (float*)(smem + 2304);   // 64 floats

    s_b1[tid] = b1[tid];
    s_w2[tid] = w2[tid];
    if (tid < CTA_M) s_part[tid] = 0.0f;
    float b2 = *b2p;
    __syncthreads();

    // prologue: both stages
    load_tiles(sb + OFF_TILES, 0, r0, tid);
    CP_COMMIT();
    load_tiles(sb + OFF_TILES + STAGE_BYTES, KT2, r0, tid);
    CP_COMMIT();

    float acc[2][8][4];
    #pragma unroll
    for (int mi = 0; mi < 2; mi++)
        #pragma unroll
        for (int ni = 0; ni < 8; ni++)
            #pragma unroll
            for (int j = 0; j < 4; j++) acc[mi][ni][j] = 0.0f;

    // per-thread ldmatrix addressing (within tile, pre-swizzle parts)
    int arow  = warp_m * 32 + (lane & 15);
    uint32_t acol = ((uint32_t)(lane >> 4)) * 16;
    int nrow  = warp_n * 64 + (((lane >> 4) & 1) << 3) + (lane & 7);
    uint32_t bcol = (((uint32_t)(lane >> 3)) & 1) << 4;

    for (int it = 0; it < NITER; it++) {
        if (it < NITER - 1)
            asm volatile("cp.async.wait_group 1;" ::: "memory");
        else
            asm volatile("cp.async.wait_group 0;" ::: "memory");
        __syncthreads();

        uint32_t st = sb + OFF_TILES + (uint32_t)(it & 1) * STAGE_BYTES;

        #pragma unroll
        for (int ks = 0; ks < 4; ks++) {
            uint32_t kb = (uint32_t)ks * 32;
            uint32_t aa[2][4];
            #pragma unroll
            for (int mi = 0; mi < 2; mi++) {
                uint32_t off = SWZ((uint32_t)((arow + mi * 16) * 128) + acol + kb);
                LDSM_X4(aa[mi], st + OFF_A + off);
            }
            uint32_t bb[8][2];
            #pragma unroll
            for (int g = 0; g < 4; g++) {
                uint32_t off = SWZ((uint32_t)((nrow + g * 16) * 128) + bcol + kb);
                uint32_t rb[4];
                LDSM_X4(rb, st + OFF_B + off);
                bb[2 * g][0] = rb[0]; bb[2 * g][1] = rb[1];
                bb[2 * g + 1][0] = rb[2]; bb[2 * g + 1][1] = rb[3];
            }
            #pragma unroll
            for (int mi = 0; mi < 2; mi++)
                #pragma unroll
                for (int ni = 0; ni < 8; ni++)
                    MMA_F16(acc[mi][ni], aa[mi], bb[ni]);
        }

        __syncthreads();
        if (it + 2 < NITER) {
            load_tiles(st, (it + 2) * KT2, r0, tid);
            CP_COMMIT();
        }
    }

    // alpha partials: relu(hdn + b1) . w2 over this warp's 64 columns
    #pragma unroll
    for (int mi = 0; mi < 2; mi++) {
        #pragma unroll
        for (int rh = 0; rh < 2; rh++) {
            float part = 0.0f;
            #pragma unroll
            for (int ni = 0; ni < 8; ni++) {
                int col0 = warp_n * 64 + ni * 8 + 2 * (lane & 3);
                float h0 = acc[mi][ni][rh * 2 + 0] + s_b1[col0];
                float h1 = acc[mi][ni][rh * 2 + 1] + s_b1[col0 + 1];
                h0 = h0 > 0.f ? h0 : 0.f;
                h1 = h1 > 0.f ? h1 : 0.f;
                part = fmaf(h0, s_w2[col0], part);
                part = fmaf(h1, s_w2[col0 + 1], part);
            }
            part += __shfl_xor_sync(0xffffffffu, part, 1);
            part += __shfl_xor_sync(0xffffffffu, part, 2);
            if ((lane & 3) == 0)
                atomicAdd(&s_part[warp_m * 32 + mi * 16 + rh * 8 + (lane >> 2)], part);
        }
    }
    __syncthreads();
    if (tid < CTA_M) {
        float z = s_part[tid] + b2;
        s_alpha[tid] = 1.0f / (1.0f + expf(-z));
    }
    __syncthreads();

    // blend/head/l2 epilogue: 8 warps x 8 words
    float* out_logits = out;
    float* out_alpha  = out + (size_t)ROWS * L;
    float* out_l2     = out_alpha + ROWS;

    #pragma unroll 1
    for (int wi = 0; wi < 8; wi++) {
        int li = wid * 8 + wi;
        size_t row = (size_t)(r0 + li);
        float al = s_alpha[li];
        float oma = 1.0f - al;
        const __half2* xh2 = (const __half2*)(g_xh + row * KX);

        float lg[L];
        #pragma unroll
        for (int l = 0; l < L; l++) lg[l] = 0.0f;
        float l2 = 0.0f;

        #pragma unroll 1
        for (int d2 = lane; d2 < D / 2; d2 += 32) {
            __half2 hh2 = xh2[d2];
            __half2 rr2 = xh2[D / 2 + d2];
            float hh[2], hr[2];
            hh[0] = __half2float(hh2.x); hh[1] = __half2float(hh2.y);
            hr[0] = __half2float(rr2.x); hr[1] = __half2float(rr2.y);
            #pragma unroll
            for (int u = 0; u < 2; u++) {
                int d = d2 * 2 + u;
                float bl = al * hh[u] + oma * hr[u];
                float df = hh[u] - hr[u];
                l2 = fmaf(df, df, l2);
                #pragma unroll
                for (int l = 0; l < L; l++)
                    lg[l] = fmaf(bl, headw[(size_t)d * L + l], lg[l]);
            }
        }
        #pragma unroll
        for (int o = 16; o > 0; o >>= 1) {
            #pragma unroll
            for (int l = 0; l < L; l++)
                lg[l] += __shfl_xor_sync(0xffffffffu, lg[l], o);
            l2 += __shfl_xor_sync(0xffffffffu, l2, o);
        }
        if (lane == 0) {
            #pragma unroll
            for (int l = 0; l < L; l++)
                out_logits[row * L + l] = lg[l] + headb[l];
            out_alpha[row] = al;
            out_l2[row] = sqrtf(l2);
        }
    }
}

extern "C" void kernel_launch(void* const* d_in, const int* in_sizes, int n_in,
                              void* d_out, int out_size)
{
    const float* hing = (const float*)d_in[0];
    const float* rob  = (const float*)d_in[1];
    const int*   hids = (const int*)d_in[2];
    const int*   rids = (const int*)d_in[3];
    // d_in[4] = num_words (unused by the reference outputs)
    const float* w1 = (const float*)d_in[5];
    const float* b1 = (const float*)d_in[6];
    const float* w2 = (const float*)d_in[7];
    const float* b2 = (const float*)d_in[8];
    const float* hw = (const float*)d_in[9];
    const float* hb = (const float*)d_in[10];
    float* out = (float*)d_out;

    cudaFuncSetAttribute(router_kernel,
                         cudaFuncAttributeMaxDynamicSharedMemorySize, SMEM_TOTAL);

    align_kernel<<<(ROWS * 2) / 8 + (KX * H) / 256, 256>>>(hing, rob, hids, rids, w1);
    router_kernel<<<ROWS / CTA_M, 256, SMEM_TOTAL>>>(b1, w2, b2, hw, hb, out);
}